// round 9
// baseline (speedup 1.0000x reference)
#include <cuda_runtime.h>
#include <math.h>

#define TT    1000
#define BB    128
#define NIN   85
#define NRNN  512
#define NOUT  33
#define MM    (TT * BB)     /* 128000 rows */
#define STEP  (BB * NRNN)   /* 65536 */
#define PF    8             /* G prefetch ring depth in diag recurrence */

typedef unsigned long long u64;

// ---------------------------------------------------------------------------
// Packed f32x2 helpers (exact IEEE fp32 per lane; 2x FFMA rate on sm_103a)
// ---------------------------------------------------------------------------
__device__ __forceinline__ u64 pack2(float lo, float hi) {
    u64 r; asm("mov.b64 %0, {%1, %2};" : "=l"(r) : "f"(lo), "f"(hi)); return r;
}
__device__ __forceinline__ void unpack2(u64 v, float& lo, float& hi) {
    asm("mov.b64 {%0, %1}, %2;" : "=f"(lo), "=f"(hi) : "l"(v));
}
__device__ __forceinline__ u64 fma2(u64 a, u64 b, u64 c) {
    u64 d; asm("fma.rn.f32x2 %0, %1, %2, %3;" : "=l"(d) : "l"(a), "l"(b), "l"(c));
    return d;
}

// ---------------------------------------------------------------------------
// Scratch (__device__ globals: module-load allocated, no runtime alloc)
// ---------------------------------------------------------------------------
__device__ float g_G[(size_t)TT * BB * NRNN];      // pre-gate, 262 MB
__device__ float g_xT[(size_t)NIN * MM];           // transposed x, 43.5 MB
__device__ int   g_cnt[NRNN];                      // sparse W_rec (fallback only)
__device__ int   g_idx[NRNN * NRNN];
__device__ float g_val[NRNN * NRNN];
__device__ int   g_diag;                           // 1 iff W_rec is diagonal
__device__ float g_wdiag[NRNN];                    // diagonal weight per column

__global__ void init_kernel() { g_diag = 1; }

// Parallel diagonal detection (coalesced in n); atomicAnd fires only on
// nonzero off-diagonals. Skipping exact zeros is bit-exact in fp32.
__global__ void detect_diag(const float* __restrict__ W) {
    int e = blockIdx.x * blockDim.x + threadIdx.x;   // 262144 threads
    int k = e >> 9;
    int n = e & (NRNN - 1);
    float w = W[(size_t)(NIN + k) * NRNN + n];
    if (k == n)          g_wdiag[n] = w;
    else if (w != 0.0f)  atomicAnd(&g_diag, 0);
}

// CSC build — only runs on non-diagonal inputs (predicated on !g_diag).
__global__ void build_csc(const float* __restrict__ W) {
    if (g_diag) return;
    if (threadIdx.x != 0) return;
    int n = blockIdx.x;
    int c = 0;
    for (int k = 0; k < NRNN; k++) {
        float w = W[(size_t)(NIN + k) * NRNN + n];
        if (w != 0.0f) {
            g_idx[n * NRNN + c] = k;
            g_val[n * NRNN + c] = w;
            c++;
        }
    }
    g_cnt[n] = c;
}

// ---------------------------------------------------------------------------
// Kernel 0d: global transpose x[M,85] -> xT[85,M]. Shared 32x32 tile.
// ---------------------------------------------------------------------------
__global__ void transpose_x(const float* __restrict__ x) {
    __shared__ float tile[32][33];
    int mb = blockIdx.x * 32;
    int kb = blockIdx.y * 32;
    int tx = threadIdx.x;                // 32
    int ty = threadIdx.y;                // 8
    #pragma unroll
    for (int i = ty; i < 32; i += 8) {
        int k = kb + tx;
        tile[i][tx] = (k < NIN) ? x[(size_t)(mb + i) * NIN + k] : 0.0f;
    }
    __syncthreads();
    #pragma unroll
    for (int i = ty; i < 32; i += 8) {
        int k = kb + i;
        if (k < NIN) g_xT[(size_t)k * MM + mb + tx] = tile[tx][i];
    }
}

// ---------------------------------------------------------------------------
// Kernel 1: G[m,n] = x[m,:] @ W_in[:,n] + b[n] + noise[m,n]
// M=128000, K=85, N=512. CTA tile 128x64, 128 threads, 8 rows x 8 cols.
// Row-pair packing: a comes pre-paired from xT (adjacent m contiguous,
// float4 copy at staging = zero packs); w broadcast-packed (w,w) at staging
// (amortized over 16 row-pairs). Inner loop: 6 LDS.128 + 32 FFMA2, NO MOVs.
// ---------------------------------------------------------------------------
#define TM 128
#define TN 64
#define KT 32
__global__ void __launch_bounds__(128, 5) phase1_kernel(
        const float* __restrict__ W,
        const float* __restrict__ bias,
        const float* __restrict__ noise) {
    __shared__ u64 As2[KT][TM / 2];      // row-pair a: 16.4 KB
    __shared__ u64 Wsb[KT][TN];          // broadcast-packed w: 16.4 KB

    int tid = threadIdx.x;               // 128 threads
    int m0  = blockIdx.x * TM;           // 1000 M-tiles
    int n0  = blockIdx.y * TN;           // 8 N-tiles
    int tx  = tid & 7;                   // col group: cols tx*8..tx*8+7
    int ty  = tid >> 3;                  // row group: rows ty*8..ty*8+7 (4 pairs)

    u64 acc[4][8] = {};                  // [row-pair][col]

    for (int k0 = 0; k0 < NIN; k0 += KT) {
        int kmax = NIN - k0; if (kmax > KT) kmax = KT;
        __syncthreads();
        // stage a: fixed k, consecutive float4 of m. LDG.128 coalesced,
        // STS.128 consecutive: conflict-free. Pairs form naturally.
        for (int idx = tid; idx < KT * (TM / 4); idx += 128) {
            int k  = idx >> 5;           // TM/4 = 32
            int r4 = idx & 31;
            float4 v;
            if (k < kmax)
                v = *reinterpret_cast<const float4*>(
                        &g_xT[(size_t)(k0 + k) * MM + m0 + r4 * 4]);
            else
                v = make_float4(0.f, 0.f, 0.f, 0.f);
            *reinterpret_cast<float4*>(&As2[k][r4 * 2]) = v;
        }
        // stage w broadcast-packed: coalesced LDG, consecutive STS.64
        for (int idx = tid; idx < KT * TN; idx += 128) {
            int k = idx >> 6;
            int n = idx & 63;
            float w = (k < kmax) ? W[(size_t)(k0 + k) * NRNN + n0 + n] : 0.0f;
            Wsb[k][n] = pack2(w, w);
        }
        __syncthreads();

        #pragma unroll 4
        for (int k = 0; k < kmax; k++) {
            ulonglong2 a01 = *reinterpret_cast<ulonglong2*>(&As2[k][ty * 4]);
            ulonglong2 a23 = *reinterpret_cast<ulonglong2*>(&As2[k][ty * 4 + 2]);
            ulonglong2 w01 = *reinterpret_cast<ulonglong2*>(&Wsb[k][tx * 8]);
            ulonglong2 w23 = *reinterpret_cast<ulonglong2*>(&Wsb[k][tx * 8 + 2]);
            ulonglong2 w45 = *reinterpret_cast<ulonglong2*>(&Wsb[k][tx * 8 + 4]);
            ulonglong2 w67 = *reinterpret_cast<ulonglong2*>(&Wsb[k][tx * 8 + 6]);
            u64 av[4] = { a01.x, a01.y, a23.x, a23.y };
            u64 wv[8] = { w01.x, w01.y, w23.x, w23.y,
                          w45.x, w45.y, w67.x, w67.y };
            #pragma unroll
            for (int p = 0; p < 4; p++)
                #pragma unroll
                for (int j = 0; j < 8; j++)
                    acc[p][j] = fma2(av[p], wv[j], acc[p][j]);
        }
    }

    float4 bb0 = *reinterpret_cast<const float4*>(&bias[n0 + tx * 8]);
    float4 bb1 = *reinterpret_cast<const float4*>(&bias[n0 + tx * 8 + 4]);
    float bb[8] = { bb0.x, bb0.y, bb0.z, bb0.w, bb1.x, bb1.y, bb1.z, bb1.w };

    #pragma unroll
    for (int p = 0; p < 4; p++) {
        float lo[8], hi[8];
        #pragma unroll
        for (int j = 0; j < 8; j++) unpack2(acc[p][j], lo[j], hi[j]);

        int m = m0 + ty * 8 + p * 2;     // rows m (lo) and m+1 (hi)
        size_t off0 = (size_t)m * NRNN + n0 + tx * 8;
        size_t off1 = off0 + NRNN;

        float4 nz0a = *reinterpret_cast<const float4*>(&noise[off0]);
        float4 nz0b = *reinterpret_cast<const float4*>(&noise[off0 + 4]);
        float4 nz1a = *reinterpret_cast<const float4*>(&noise[off1]);
        float4 nz1b = *reinterpret_cast<const float4*>(&noise[off1 + 4]);

        float4 o;
        o.x = lo[0]+bb[0]+nz0a.x; o.y = lo[1]+bb[1]+nz0a.y;
        o.z = lo[2]+bb[2]+nz0a.z; o.w = lo[3]+bb[3]+nz0a.w;
        *reinterpret_cast<float4*>(&g_G[off0]) = o;
        o.x = lo[4]+bb[4]+nz0b.x; o.y = lo[5]+bb[5]+nz0b.y;
        o.z = lo[6]+bb[6]+nz0b.z; o.w = lo[7]+bb[7]+nz0b.w;
        *reinterpret_cast<float4*>(&g_G[off0 + 4]) = o;
        o.x = hi[0]+bb[0]+nz1a.x; o.y = hi[1]+bb[1]+nz1a.y;
        o.z = hi[2]+bb[2]+nz1a.z; o.w = hi[3]+bb[3]+nz1a.w;
        *reinterpret_cast<float4*>(&g_G[off1]) = o;
        o.x = hi[4]+bb[4]+nz1b.x; o.y = hi[5]+bb[5]+nz1b.y;
        o.z = hi[6]+bb[6]+nz1b.z; o.w = hi[7]+bb[7]+nz1b.w;
        *reinterpret_cast<float4*>(&g_G[off1 + 4]) = o;
    }
}

// ---------------------------------------------------------------------------
// Kernel 2a (fast path): pure-diagonal recurrence. Independent chains,
// h in a register, no barriers, depth-PF G prefetch ring.
// ---------------------------------------------------------------------------
__global__ void rec_diag_kernel(float* __restrict__ Hout) {
    if (!g_diag) return;
    int e = blockIdx.x * blockDim.x + threadIdx.x;   // 65536 threads
    int n = e & (NRNN - 1);
    float w = g_wdiag[n];

    const float* Gp = g_G + e;
    float*       Hp = Hout + e;

    float buf[PF];
    #pragma unroll
    for (int i = 0; i < PF; i++) buf[i] = Gp[(size_t)i * STEP];

    float h = 0.0f;
    for (int t0 = 0; t0 < TT; t0 += PF) {
        #pragma unroll
        for (int i = 0; i < PF; i++) {
            int t = t0 + i;
            float g = buf[i];
            int tf = t + PF;
            if (tf < TT) buf[i] = Gp[(size_t)tf * STEP];
            float acc = fmaf(w, h, g);
            float sp  = fmaxf(acc, 0.0f) + __logf(1.0f + __expf(-fabsf(acc)));
            h = 0.8f * h + 0.2f * sp;
            Hp[(size_t)t * STEP] = h;
        }
    }
}

// ---------------------------------------------------------------------------
// Kernel 2b (generic fallback): barriered sparse recurrence, one CTA/batch.
// ---------------------------------------------------------------------------
__global__ void rec_generic_kernel(float* __restrict__ Hout) {
    if (g_diag) return;
    __shared__ float hs[2][NRNN];
    int n = threadIdx.x;
    int b = blockIdx.x;

    hs[0][n] = 0.0f;

    int cnt = g_cnt[n];
    int   ki[4];
    float wv[4];
    #pragma unroll
    for (int j = 0; j < 4; j++) {
        if (j < cnt) { ki[j] = g_idx[n * NRNN + j]; wv[j] = g_val[n * NRNN + j]; }
        else         { ki[j] = 0;                    wv[j] = 0.0f; }
    }

    const float* Gb = g_G + (size_t)b * NRNN + n;
    float*       Hb = Hout + (size_t)b * NRNN + n;
    __syncthreads();

    int p = 0;
    float gcur = Gb[0];
    for (int t = 0; t < TT; t++) {
        int tn = (t + 1 < TT) ? (t + 1) : t;
        float gnext = Gb[(size_t)tn * STEP];

        float acc = gcur;
        acc = fmaf(wv[0], hs[p][ki[0]], acc);
        acc = fmaf(wv[1], hs[p][ki[1]], acc);
        acc = fmaf(wv[2], hs[p][ki[2]], acc);
        acc = fmaf(wv[3], hs[p][ki[3]], acc);
        for (int j = 4; j < cnt; j++)
            acc = fmaf(g_val[n * NRNN + j], hs[p][g_idx[n * NRNN + j]], acc);

        float sp = fmaxf(acc, 0.0f) + __logf(1.0f + __expf(-fabsf(acc)));
        float hn = 0.8f * hs[p][n] + 0.2f * sp;

        hs[p ^ 1][n] = hn;
        Hb[(size_t)t * STEP] = hn;
        __syncthreads();
        p ^= 1;
        gcur = gnext;
    }
}

// ---------------------------------------------------------------------------
// Kernel 3: y[m,o] = sigmoid(h[m,:] @ W_out[:,o] + b_out[o])
// o2-split groups x 4 interleaved rows/thread; conflict-free stride-9 LDS.
// ---------------------------------------------------------------------------
#define P3BK 8
#define P3PAD (P3BK + 1)
#define NO2  17
#define NO2G 9
__global__ void __launch_bounds__(256) phase3_kernel(
        const float* __restrict__ Hin,
        const float* __restrict__ Wout,
        const float* __restrict__ bout,
        float* __restrict__ y) {
    __shared__ float hsh[512][P3PAD];
    __shared__ u64   wsh2[P3BK][NO2];

    int tid = threadIdx.x;                        // 256 threads
    int g   = tid >> 7;
    int t   = tid & 127;
    int m0  = blockIdx.x * 512;                   // 250 blocks
    int ob  = g * NO2G;

    u64 acc[4][NO2G] = {};

    for (int k0 = 0; k0 < NRNN; k0 += P3BK) {
        __syncthreads();
        for (int idx = tid; idx < 512 * P3BK; idx += 256) {
            int r = idx >> 3;
            int k = idx & (P3BK - 1);
            hsh[r][k] = Hin[(size_t)(m0 + r) * NRNN + k0 + k];
        }
        for (int idx = tid; idx < P3BK * NO2; idx += 256) {
            int k  = idx / NO2;
            int o2 = idx - k * NO2;
            float lo = Wout[(size_t)(k0 + k) * NOUT + 2 * o2];
            float hi = (2 * o2 + 1 < NOUT) ? Wout[(size_t)(k0 + k) * NOUT + 2 * o2 + 1] : 0.0f;
            wsh2[k][o2] = pack2(lo, hi);
        }
        __syncthreads();

        #pragma unroll
        for (int kk = 0; kk < P3BK; kk++) {
            u64 hp[4];
            #pragma unroll
            for (int i = 0; i < 4; i++) {
                float hv = hsh[t + i * 128][kk];
                hp[i] = pack2(hv, hv);
            }
            #pragma unroll
            for (int j = 0; j < NO2G; j++) {
                int o2 = ob + j;
                u64 w = (o2 < NO2) ? wsh2[kk][o2] : 0ull;
                #pragma unroll
                for (int i = 0; i < 4; i++)
                    acc[i][j] = fma2(hp[i], w, acc[i][j]);
            }
        }
    }

    #pragma unroll
    for (int j = 0; j < NO2G; j++) {
        int o2 = ob + j;
        if (o2 >= NO2) continue;
        float b0 = bout[2 * o2];
        float b1 = (2 * o2 + 1 < NOUT) ? bout[2 * o2 + 1] : 0.0f;
        #pragma unroll
        for (int i = 0; i < 4; i++) {
            int r = m0 + t + i * 128;
            float v0, v1;
            unpack2(acc[i][j], v0, v1);
            y[(size_t)r * NOUT + 2 * o2] = 1.0f / (1.0f + __expf(-(v0 + b0)));
            if (2 * o2 + 1 < NOUT)
                y[(size_t)r * NOUT + 2 * o2 + 1] = 1.0f / (1.0f + __expf(-(v1 + b1)));
        }
    }
}

// ---------------------------------------------------------------------------
// Launch. Inputs: x, W, b, W_out, b_out, noise.
// Output: [y_hat (T*B*33) | h (T*B*512)] fp32.
// ---------------------------------------------------------------------------
extern "C" void kernel_launch(void* const* d_in, const int* in_sizes, int n_in,
                              void* d_out, int out_size) {
    const float* x     = (const float*)d_in[0];
    const float* W     = (const float*)d_in[1];
    const float* b     = (const float*)d_in[2];
    const float* W_out = (const float*)d_in[3];
    const float* b_out = (const float*)d_in[4];
    const float* noise = (const float*)d_in[5];

    float* y = (float*)d_out;
    float* h = (float*)d_out + (size_t)TT * BB * NOUT;

    init_kernel<<<1, 1>>>();
    detect_diag<<<(NRNN * NRNN) / 256, 256>>>(W);
    build_csc<<<NRNN, 32>>>(W);                              // fallback only
    transpose_x<<<dim3(MM / 32, (NIN + 31) / 32), dim3(32, 8)>>>(x);
    phase1_kernel<<<dim3(MM / TM, NRNN / TN), 128>>>(W, b, noise);
    rec_diag_kernel<<<(BB * NRNN) / 256, 256>>>(h);          // fast path
    rec_generic_kernel<<<BB, NRNN>>>(h);                     // fallback
    phase3_kernel<<<(TT * BB) / 512, 256>>>(h, W_out, b_out, y);
}

// round 10
// speedup vs baseline: 1.5785x; 1.5785x over previous
#include <cuda_runtime.h>
#include <math.h>

#define TT    1000
#define BB    128
#define NIN   85
#define NRNN  512
#define NOUT  33
#define MM    (TT * BB)     /* 128000 rows */
#define STEP  (BB * NRNN)   /* 65536 */
#define PF    8             /* G prefetch ring depth in diag recurrence */

typedef unsigned long long u64;

// ---------------------------------------------------------------------------
// Packed f32x2 helpers (exact IEEE fp32 per lane; 2x FFMA rate on sm_103a)
// ---------------------------------------------------------------------------
__device__ __forceinline__ u64 pack2(float lo, float hi) {
    u64 r; asm("mov.b64 %0, {%1, %2};" : "=l"(r) : "f"(lo), "f"(hi)); return r;
}
__device__ __forceinline__ void unpack2(u64 v, float& lo, float& hi) {
    asm("mov.b64 {%0, %1}, %2;" : "=f"(lo), "=f"(hi) : "l"(v));
}
__device__ __forceinline__ u64 fma2(u64 a, u64 b, u64 c) {
    u64 d; asm("fma.rn.f32x2 %0, %1, %2, %3;" : "=l"(d) : "l"(a), "l"(b), "l"(c));
    return d;
}

// ---------------------------------------------------------------------------
// Scratch (__device__ globals: module-load allocated, no runtime alloc)
// ---------------------------------------------------------------------------
__device__ float g_G[(size_t)TT * BB * NRNN];      // pre-gate, 262 MB
__device__ float g_xT[(size_t)NIN * MM];           // transposed x, 43.5 MB
__device__ int   g_cnt[NRNN];                      // sparse W_rec (fallback only)
__device__ int   g_idx[NRNN * NRNN];
__device__ float g_val[NRNN * NRNN];
__device__ int   g_diag;                           // 1 iff W_rec is diagonal
__device__ float g_wdiag[NRNN];                    // diagonal weight per column

__global__ void init_kernel() { g_diag = 1; }

// Parallel diagonal detection (coalesced in n); atomicAnd fires only on
// nonzero off-diagonals. Skipping exact zeros is bit-exact in fp32.
__global__ void detect_diag(const float* __restrict__ W) {
    int e = blockIdx.x * blockDim.x + threadIdx.x;   // 262144 threads
    int k = e >> 9;
    int n = e & (NRNN - 1);
    float w = W[(size_t)(NIN + k) * NRNN + n];
    if (k == n)          g_wdiag[n] = w;
    else if (w != 0.0f)  atomicAnd(&g_diag, 0);
}

// CSC build — only runs on non-diagonal inputs (predicated on !g_diag).
__global__ void build_csc(const float* __restrict__ W) {
    if (g_diag) return;
    if (threadIdx.x != 0) return;
    int n = blockIdx.x;
    int c = 0;
    for (int k = 0; k < NRNN; k++) {
        float w = W[(size_t)(NIN + k) * NRNN + n];
        if (w != 0.0f) {
            g_idx[n * NRNN + c] = k;
            g_val[n * NRNN + c] = w;
            c++;
        }
    }
    g_cnt[n] = c;
}

// ---------------------------------------------------------------------------
// Kernel 0d: global transpose x[M,85] -> xT[85,M]. Shared 32x32 tile.
// ---------------------------------------------------------------------------
__global__ void transpose_x(const float* __restrict__ x) {
    __shared__ float tile[32][33];
    int mb = blockIdx.x * 32;
    int kb = blockIdx.y * 32;
    int tx = threadIdx.x;                // 32
    int ty = threadIdx.y;                // 8
    #pragma unroll
    for (int i = ty; i < 32; i += 8) {
        int k = kb + tx;
        tile[i][tx] = (k < NIN) ? x[(size_t)(mb + i) * NIN + k] : 0.0f;
    }
    __syncthreads();
    #pragma unroll
    for (int i = ty; i < 32; i += 8) {
        int k = kb + i;
        if (k < NIN) g_xT[(size_t)k * MM + mb + tx] = tile[tx][i];
    }
}

// ---------------------------------------------------------------------------
// Kernel 1: G[m,n] = x[m,:] @ W_in[:,n] + b[n] + noise[m,n]
// M=128000, K=85, N=512. CTA tile 128x64, 128 threads, 8 rows x 8 cols.
// Row-pair accumulators: a comes pre-paired from xT (zero packs), w
// broadcast-packed (w,w) at staging. Strided column mapping (group g ->
// cols g*16 + tx*2 + {0,1}) makes every inner-loop LDS conflict-free.
// launch_bounds(128,4): reg cap 128, no spills (R9's (128,5) cap spilled).
// Inner loop per k: 6 LDS.128 + 32 FFMA2, zero MOVs.
// ---------------------------------------------------------------------------
#define TM 128
#define TN 64
#define KT 32
__global__ void __launch_bounds__(128, 4) phase1_kernel(
        const float* __restrict__ W,
        const float* __restrict__ bias,
        const float* __restrict__ noise) {
    __shared__ u64 As2[KT][TM / 2];      // row-pair a: 16.4 KB
    __shared__ u64 Wsb[KT][TN];          // broadcast-packed w: 16.4 KB

    int tid = threadIdx.x;               // 128 threads
    int m0  = blockIdx.x * TM;           // 1000 M-tiles
    int n0  = blockIdx.y * TN;           // 8 N-tiles
    int tx  = tid & 7;                   // col lane: cols g*16 + tx*2 + {0,1}
    int ty  = tid >> 3;                  // row group: rows ty*8..ty*8+7 (4 pairs)

    u64 acc[4][8] = {};                  // [row-pair][g*2 + d]

    for (int k0 = 0; k0 < NIN; k0 += KT) {
        int kmax = NIN - k0; if (kmax > KT) kmax = KT;
        __syncthreads();
        // stage a: fixed k, consecutive float4 of m. LDG.128 coalesced,
        // STS.128 consecutive: conflict-free. Row pairs form naturally.
        for (int idx = tid; idx < KT * (TM / 4); idx += 128) {
            int k  = idx >> 5;           // TM/4 = 32
            int r4 = idx & 31;
            float4 v;
            if (k < kmax)
                v = *reinterpret_cast<const float4*>(
                        &g_xT[(size_t)(k0 + k) * MM + m0 + r4 * 4]);
            else
                v = make_float4(0.f, 0.f, 0.f, 0.f);
            *reinterpret_cast<float4*>(&As2[k][r4 * 2]) = v;
        }
        // stage w broadcast-packed: coalesced LDG, consecutive STS.64
        for (int idx = tid; idx < KT * TN; idx += 128) {
            int k = idx >> 6;
            int n = idx & 63;
            float w = (k < kmax) ? W[(size_t)(k0 + k) * NRNN + n0 + n] : 0.0f;
            Wsb[k][n] = pack2(w, w);
        }
        __syncthreads();

        #pragma unroll 4
        for (int k = 0; k < kmax; k++) {
            // a: ty in 0..3 per warp, 32B stride -> conflict-free
            ulonglong2 a01 = *reinterpret_cast<ulonglong2*>(&As2[k][ty * 4]);
            ulonglong2 a23 = *reinterpret_cast<ulonglong2*>(&As2[k][ty * 4 + 2]);
            #pragma unroll
            for (int g = 0; g < 4; g++) {
                // w: lane addr tx*16B spans 128B -> conflict-free LDS.128
                ulonglong2 w = *reinterpret_cast<ulonglong2*>(
                    &Wsb[k][g * 16 + tx * 2]);
                acc[0][g*2]   = fma2(a01.x, w.x, acc[0][g*2]);
                acc[0][g*2+1] = fma2(a01.x, w.y, acc[0][g*2+1]);
                acc[1][g*2]   = fma2(a01.y, w.x, acc[1][g*2]);
                acc[1][g*2+1] = fma2(a01.y, w.y, acc[1][g*2+1]);
                acc[2][g*2]   = fma2(a23.x, w.x, acc[2][g*2]);
                acc[2][g*2+1] = fma2(a23.x, w.y, acc[2][g*2+1]);
                acc[3][g*2]   = fma2(a23.y, w.x, acc[3][g*2]);
                acc[3][g*2+1] = fma2(a23.y, w.y, acc[3][g*2+1]);
            }
        }
    }

    // epilogue: acc[p][g*2+d] = rows (m, m+1) x column g*16 + tx*2 + d
    float2 bb[4];
    #pragma unroll
    for (int g = 0; g < 4; g++)
        bb[g] = *reinterpret_cast<const float2*>(&bias[n0 + g * 16 + tx * 2]);

    #pragma unroll
    for (int p = 0; p < 4; p++) {
        int m = m0 + ty * 8 + p * 2;
        size_t row0 = (size_t)m * NRNN + n0;
        size_t row1 = row0 + NRNN;
        #pragma unroll
        for (int g = 0; g < 4; g++) {
            int c = g * 16 + tx * 2;
            float l0, h0, l1, h1;
            unpack2(acc[p][g*2],   l0, h0);   // (row m, row m+1) col c
            unpack2(acc[p][g*2+1], l1, h1);   // (row m, row m+1) col c+1
            float2 nz0 = *reinterpret_cast<const float2*>(&noise[row0 + c]);
            float2 nz1 = *reinterpret_cast<const float2*>(&noise[row1 + c]);
            float2 o0, o1;
            o0.x = l0 + bb[g].x + nz0.x;
            o0.y = l1 + bb[g].y + nz0.y;
            o1.x = h0 + bb[g].x + nz1.x;
            o1.y = h1 + bb[g].y + nz1.y;
            *reinterpret_cast<float2*>(&g_G[row0 + c]) = o0;
            *reinterpret_cast<float2*>(&g_G[row1 + c]) = o1;
        }
    }
}

// ---------------------------------------------------------------------------
// Kernel 2a (fast path): pure-diagonal recurrence. Independent chains,
// h in a register, no barriers, depth-PF G prefetch ring.
// ---------------------------------------------------------------------------
__global__ void rec_diag_kernel(float* __restrict__ Hout) {
    if (!g_diag) return;
    int e = blockIdx.x * blockDim.x + threadIdx.x;   // 65536 threads
    int n = e & (NRNN - 1);
    float w = g_wdiag[n];

    const float* Gp = g_G + e;
    float*       Hp = Hout + e;

    float buf[PF];
    #pragma unroll
    for (int i = 0; i < PF; i++) buf[i] = Gp[(size_t)i * STEP];

    float h = 0.0f;
    for (int t0 = 0; t0 < TT; t0 += PF) {
        #pragma unroll
        for (int i = 0; i < PF; i++) {
            int t = t0 + i;
            float g = buf[i];
            int tf = t + PF;
            if (tf < TT) buf[i] = Gp[(size_t)tf * STEP];
            float acc = fmaf(w, h, g);
            float sp  = fmaxf(acc, 0.0f) + __logf(1.0f + __expf(-fabsf(acc)));
            h = 0.8f * h + 0.2f * sp;
            Hp[(size_t)t * STEP] = h;
        }
    }
}

// ---------------------------------------------------------------------------
// Kernel 2b (generic fallback): barriered sparse recurrence, one CTA/batch.
// ---------------------------------------------------------------------------
__global__ void rec_generic_kernel(float* __restrict__ Hout) {
    if (g_diag) return;
    __shared__ float hs[2][NRNN];
    int n = threadIdx.x;
    int b = blockIdx.x;

    hs[0][n] = 0.0f;

    int cnt = g_cnt[n];
    int   ki[4];
    float wv[4];
    #pragma unroll
    for (int j = 0; j < 4; j++) {
        if (j < cnt) { ki[j] = g_idx[n * NRNN + j]; wv[j] = g_val[n * NRNN + j]; }
        else         { ki[j] = 0;                    wv[j] = 0.0f; }
    }

    const float* Gb = g_G + (size_t)b * NRNN + n;
    float*       Hb = Hout + (size_t)b * NRNN + n;
    __syncthreads();

    int p = 0;
    float gcur = Gb[0];
    for (int t = 0; t < TT; t++) {
        int tn = (t + 1 < TT) ? (t + 1) : t;
        float gnext = Gb[(size_t)tn * STEP];

        float acc = gcur;
        acc = fmaf(wv[0], hs[p][ki[0]], acc);
        acc = fmaf(wv[1], hs[p][ki[1]], acc);
        acc = fmaf(wv[2], hs[p][ki[2]], acc);
        acc = fmaf(wv[3], hs[p][ki[3]], acc);
        for (int j = 4; j < cnt; j++)
            acc = fmaf(g_val[n * NRNN + j], hs[p][g_idx[n * NRNN + j]], acc);

        float sp = fmaxf(acc, 0.0f) + __logf(1.0f + __expf(-fabsf(acc)));
        float hn = 0.8f * hs[p][n] + 0.2f * sp;

        hs[p ^ 1][n] = hn;
        Hb[(size_t)t * STEP] = hn;
        __syncthreads();
        p ^= 1;
        gcur = gnext;
    }
}

// ---------------------------------------------------------------------------
// Kernel 3: y[m,o] = sigmoid(h[m,:] @ W_out[:,o] + b_out[o])
// o2-split groups x 4 interleaved rows/thread; conflict-free stride-9 LDS.
// ---------------------------------------------------------------------------
#define P3BK 8
#define P3PAD (P3BK + 1)
#define NO2  17
#define NO2G 9
__global__ void __launch_bounds__(256) phase3_kernel(
        const float* __restrict__ Hin,
        const float* __restrict__ Wout,
        const float* __restrict__ bout,
        float* __restrict__ y) {
    __shared__ float hsh[512][P3PAD];
    __shared__ u64   wsh2[P3BK][NO2];

    int tid = threadIdx.x;                        // 256 threads
    int g   = tid >> 7;
    int t   = tid & 127;
    int m0  = blockIdx.x * 512;                   // 250 blocks
    int ob  = g * NO2G;

    u64 acc[4][NO2G] = {};

    for (int k0 = 0; k0 < NRNN; k0 += P3BK) {
        __syncthreads();
        for (int idx = tid; idx < 512 * P3BK; idx += 256) {
            int r = idx >> 3;
            int k = idx & (P3BK - 1);
            hsh[r][k] = Hin[(size_t)(m0 + r) * NRNN + k0 + k];
        }
        for (int idx = tid; idx < P3BK * NO2; idx += 256) {
            int k  = idx / NO2;
            int o2 = idx - k * NO2;
            float lo = Wout[(size_t)(k0 + k) * NOUT + 2 * o2];
            float hi = (2 * o2 + 1 < NOUT) ? Wout[(size_t)(k0 + k) * NOUT + 2 * o2 + 1] : 0.0f;
            wsh2[k][o2] = pack2(lo, hi);
        }
        __syncthreads();

        #pragma unroll
        for (int kk = 0; kk < P3BK; kk++) {
            u64 hp[4];
            #pragma unroll
            for (int i = 0; i < 4; i++) {
                float hv = hsh[t + i * 128][kk];
                hp[i] = pack2(hv, hv);
            }
            #pragma unroll
            for (int j = 0; j < NO2G; j++) {
                int o2 = ob + j;
                u64 w = (o2 < NO2) ? wsh2[kk][o2] : 0ull;
                #pragma unroll
                for (int i = 0; i < 4; i++)
                    acc[i][j] = fma2(hp[i], w, acc[i][j]);
            }
        }
    }

    #pragma unroll
    for (int j = 0; j < NO2G; j++) {
        int o2 = ob + j;
        if (o2 >= NO2) continue;
        float b0 = bout[2 * o2];
        float b1 = (2 * o2 + 1 < NOUT) ? bout[2 * o2 + 1] : 0.0f;
        #pragma unroll
        for (int i = 0; i < 4; i++) {
            int r = m0 + t + i * 128;
            float v0, v1;
            unpack2(acc[i][j], v0, v1);
            y[(size_t)r * NOUT + 2 * o2] = 1.0f / (1.0f + __expf(-(v0 + b0)));
            if (2 * o2 + 1 < NOUT)
                y[(size_t)r * NOUT + 2 * o2 + 1] = 1.0f / (1.0f + __expf(-(v1 + b1)));
        }
    }
}

// ---------------------------------------------------------------------------
// Launch. Inputs: x, W, b, W_out, b_out, noise.
// Output: [y_hat (T*B*33) | h (T*B*512)] fp32.
// ---------------------------------------------------------------------------
extern "C" void kernel_launch(void* const* d_in, const int* in_sizes, int n_in,
                              void* d_out, int out_size) {
    const float* x     = (const float*)d_in[0];
    const float* W     = (const float*)d_in[1];
    const float* b     = (const float*)d_in[2];
    const float* W_out = (const float*)d_in[3];
    const float* b_out = (const float*)d_in[4];
    const float* noise = (const float*)d_in[5];

    float* y = (float*)d_out;
    float* h = (float*)d_out + (size_t)TT * BB * NOUT;

    init_kernel<<<1, 1>>>();
    detect_diag<<<(NRNN * NRNN) / 256, 256>>>(W);
    build_csc<<<NRNN, 32>>>(W);                              // fallback only
    transpose_x<<<dim3(MM / 32, (NIN + 31) / 32), dim3(32, 8)>>>(x);
    phase1_kernel<<<dim3(MM / TM, NRNN / TN), 128>>>(W, b, noise);
    rec_diag_kernel<<<(BB * NRNN) / 256, 256>>>(h);          // fast path
    rec_generic_kernel<<<BB, NRNN>>>(h);                     // fallback
    phase3_kernel<<<(TT * BB) / 512, 256>>>(h, W_out, b_out, y);
}